// round 16
// baseline (speedup 1.0000x reference)
#include <cuda_runtime.h>

typedef unsigned int u32;

#define HID        50
#define ROW_W      16
#define W1_BASE    0
#define HID_BASE   64
#define HID_STRIDE (HID * ROW_W)                 // 800
#define WO_BASE    (HID_BASE + 3 * HID_STRIDE)   // 2464
#define SC_BASE    (WO_BASE + 2 * ROW_W)         // 2496
#define PACK_WORDS (SC_BASE + 8)                 // 2504 words (~10 KB)

#define TBL_DIM    255
#define TBL_SIZE   (TBL_DIM * TBL_DIM)           // 65025

#define MAGIC_F 12582912.0f                      // 1.5 * 2^23
#define MAGIC_I 0x4B400000

__device__ u32 g_scales[8];                      // 0=input absmax, 1..5=W absmax (float bits)
__device__ u32 g_abar = 0;                       // arrival counter
__device__ __align__(16) u32 g_packed[PACK_WORDS];
__device__ float2 g_table[TBL_SIZE];

// round-half-even(x * rscale) then clip to +/-127 (reciprocal-multiply form)
__device__ __forceinline__ int q8m(float x, float rscale) {
    float r = rintf(x * rscale);
    r = fminf(fmaxf(r, -127.0f), 127.0f);
    return (int)r;
}

__device__ __forceinline__ float fmax4(float4 a) {
    return fmaxf(fmaxf(fabsf(a.x), fabsf(a.y)), fmaxf(fabsf(a.z), fabsf(a.w)));
}

// ---------------------------------------------------------------------------
// K1: input absmax blocks (4 independent float4 loads/thread -> MLP=4) +
// weight blocks that pack their OWN layer inline. Last arriver does the tiny
// in_scale-dependent epilogue (W1 words + scale constants) and resets state.
// ---------------------------------------------------------------------------
__global__ void __launch_bounds__(256) absmax_prep_kernel(
        const float* __restrict__ z, const float* __restrict__ t, int n, int nb_in,
        const float* __restrict__ W1, const float* __restrict__ b1,
        const float* __restrict__ W2, const float* __restrict__ b2,
        const float* __restrict__ W3, const float* __restrict__ b3,
        const float* __restrict__ W4, const float* __restrict__ b4,
        const float* __restrict__ Wo, const float* __restrict__ bo) {
    __shared__ float red[8];
    __shared__ float swmax;
    __shared__ int  slast;
    int b = blockIdx.x, tid = threadIdx.x;
    float m = 0.0f;
    int slot;
    int w = -1;

    // ---- phase 1: abs-max slice ----
    if (b < nb_in) {
        slot = 0;
        int nv = n >> 2;                          // float4 count per array
        int total = 2 * nv;                       // combined [z | t] float4 space
        const float4* zv = reinterpret_cast<const float4*>(z);
        const float4* tv = reinterpret_cast<const float4*>(t);
        int base = b * 1024 + tid;                // block tile = 1024 float4
        // 4 independent predicated loads (front-batched -> MLP ~4)
        float m0 = 0.f, m1 = 0.f, m2 = 0.f, m3 = 0.f;
        int j0 = base, j1 = base + 256, j2 = base + 512, j3 = base + 768;
        if (j0 < total) m0 = fmax4(j0 < nv ? zv[j0] : tv[j0 - nv]);
        if (j1 < total) m1 = fmax4(j1 < nv ? zv[j1] : tv[j1 - nv]);
        if (j2 < total) m2 = fmax4(j2 < nv ? zv[j2] : tv[j2 - nv]);
        if (j3 < total) m3 = fmax4(j3 < nv ? zv[j3] : tv[j3 - nv]);
        m = fmaxf(fmaxf(m0, m1), fmaxf(m2, m3));
        if (b == 0 && tid == 0)                   // scalar tail (n % 4)
            for (int k = (n >> 2) << 2; k < n; ++k)
                m = fmaxf(m, fmaxf(fabsf(z[k]), fabsf(t[k])));
    } else {
        w = b - nb_in;                            // 0..4
        slot = 1 + w;
        const float* W = (w == 0) ? W1 : (w == 1) ? W2 : (w == 2) ? W3 : (w == 3) ? W4 : Wo;
        int sz = (w == 0 || w == 4) ? 100 : 2500;
        for (int i = tid; i < sz; i += 256) m = fmaxf(m, fabsf(W[i]));
    }

    // block reduction -> swmax (all threads) + publish to g_scales[slot]
#pragma unroll
    for (int o = 16; o > 0; o >>= 1)
        m = fmaxf(m, __shfl_xor_sync(0xFFFFFFFFu, m, o));
    if ((tid & 31) == 0) red[tid >> 5] = m;
    __syncthreads();
    if (tid == 0) {
        float mm = red[0];
#pragma unroll
        for (int s = 1; s < 8; ++s) mm = fmaxf(mm, red[s]);
        swmax = mm;
        atomicMax(&g_scales[slot], __float_as_uint(mm));  // |x|>=0: int order == float order
    }
    __syncthreads();

    // ---- phase 2 (weight blocks only): pack own layer using own swmax ----
    if (w >= 1 && w <= 3) {                      // hidden layer l = w-1
        int l = w - 1;
        const float* Wm = (l == 0) ? W2 : (l == 1) ? W3 : W4;
        const float* bm = (l == 0) ? b2 : (l == 1) ? b3 : b4;
        float ws  = fmaxf(swmax, 1e-8f) / 127.0f;
        float rws = 1.0f / ws;
        float rbs = 127.0f * rws;                // 1/(ACT_SCALE*ws)
        for (int u = tid; u < 650; u += 256) {   // 50 neurons x 13 words
            int j = u / 13, ww = u % 13;
            u32 word = 0;
#pragma unroll
            for (int e = 0; e < 4; ++e) {
                int k = 4 * ww + e, q;
                if (ww == 12 && e == 2)     q = q8m(bm[j], rbs);
                else if (k < HID)           q = q8m(Wm[j * HID + k], rws);
                else                        q = 0;
                word |= (u32)(q & 0xFF) << (8 * e);
            }
            g_packed[HID_BASE + l * HID_STRIDE + j * ROW_W + ww] = word;
        }
    } else if (w == 4) {                         // output layer: 2 x 13 words
        float ws  = fmaxf(swmax, 1e-8f) / 127.0f;
        float rws = 1.0f / ws;
        float rbs = 127.0f * rws;
        if (tid < 26) {
            int j = tid / 13, ww = tid % 13;
            u32 word = 0;
#pragma unroll
            for (int e = 0; e < 4; ++e) {
                int k = 4 * ww + e, q;
                if (ww == 12 && e == 2)     q = q8m(bo[j], rbs);
                else if (k < HID)           q = q8m(Wo[j * HID + k], rws);
                else                        q = 0;
                word |= (u32)(q & 0xFF) << (8 * e);
            }
            g_packed[WO_BASE + j * ROW_W + ww] = word;
        }
    }
    // pad words (13..15 of each row) are never read by the table kernel: skip.

    // ---- arrival: bar.sync makes block's writes visible to tid0; tid0's
    // gpu-scope fence orders them cumulatively (CG grid-sync pattern) ----
    __syncthreads();
    if (tid == 0) {
        __threadfence();
        u32 old = atomicAdd(&g_abar, 1u);
        slast = (old == gridDim.x - 1) ? 1 : 0;
    }
    __syncthreads();
    if (!slast) return;
    __threadfence();                             // acquire

    volatile u32* vs = g_scales;
    float in_scale = fmaxf(__uint_as_float(vs[0]), 1e-8f) / 127.0f;
    float ws0      = fmaxf(__uint_as_float(vs[1]), 1e-8f) / 127.0f;
    float rws0 = 1.0f / ws0;
    float rb1  = 1.0f / (in_scale * ws0);        // L1 bias reciprocal

    // W1: one word per neuron (+zero pad to 64)
    if (tid < HID_BASE) {
        u32 word = 0;
        if (tid < HID) {
            int q0 = q8m(W1[tid * 2 + 0], rws0);
            int q1 = q8m(W1[tid * 2 + 1], rws0);
            int bi = q8m(b1[tid], rb1);
            word = (u32)(q0 & 0xFF) | ((u32)(q1 & 0xFF) << 8) | ((u32)(bi & 0xFF) << 16);
        }
        g_packed[W1_BASE + tid] = word;
    }
    if (tid == 96) {
        float ws1 = fmaxf(__uint_as_float(vs[2]), 1e-8f) / 127.0f;
        float ws2 = fmaxf(__uint_as_float(vs[3]), 1e-8f) / 127.0f;
        float ws3 = fmaxf(__uint_as_float(vs[4]), 1e-8f) / 127.0f;
        float wso = fmaxf(__uint_as_float(vs[5]), 1e-8f) / 127.0f;
        g_packed[SC_BASE + 1] = __float_as_uint(in_scale * ws0 * 127.0f);   // L1 quant scale
        g_packed[SC_BASE + 2] = __float_as_uint(ws1);
        g_packed[SC_BASE + 3] = __float_as_uint(ws2);
        g_packed[SC_BASE + 4] = __float_as_uint(ws3);
        g_packed[SC_BASE + 5] = __float_as_uint((1.0f / 127.0f) * wso);     // output scale
        g_packed[SC_BASE + 6] = __float_as_uint(1.0f / in_scale);           // gather reciprocal
    }
    __syncthreads();
    if (tid < 8) g_scales[tid] = 0u;             // reset atomic slots for next replay
    if (tid == 0) g_abar = 0u;                   // reset arrival counter
}

// ---------------------------------------------------------------------------
// MLP core (int8 dp4a, exact int32 accumulation), dual-cell variant.
// ---------------------------------------------------------------------------
__device__ __forceinline__ u32 quant_act(int acc, float scale) {
    float d = __int_as_float(MAGIC_I + acc) - MAGIC_F;             // exact int->float
    int k = __float_as_int(fmaf(d, scale, MAGIC_F)) - MAGIC_I;     // rne(d*scale)
    k = max(-127, min(127, k));
    return (u32)k;                                                 // low byte = int8 k
}

__device__ __forceinline__ u32 pack4(u32 u0, u32 u1, u32 u2, u32 u3) {
    return __byte_perm(__byte_perm(u0, u1, 0x0040),
                       __byte_perm(u2, u3, 0x0040), 0x5410);
}

__device__ __forceinline__ void hidden_layer2(const u32* __restrict__ sw,
                                              const u32 aA[13], const u32 aB[13],
                                              u32 oA[13], u32 oB[13], float scale) {
#pragma unroll
    for (int jw = 0; jw < 13; ++jw) {
        const int nj = (jw == 12) ? 2 : 4;
        u32 uA[4], uB[4];
#pragma unroll
        for (int r = 0; r < nj; ++r) {
            const u32* wr = sw + (jw * 4 + r) * ROW_W;
            uint4 w0 = *reinterpret_cast<const uint4*>(wr);
            uint4 w1 = *reinterpret_cast<const uint4*>(wr + 4);
            uint4 w2 = *reinterpret_cast<const uint4*>(wr + 8);
            u32   wl = wr[12];
            int a = 0, b = 0;
            a = __dp4a((int)aA[0],  (int)w0.x, a);  b = __dp4a((int)aB[0],  (int)w0.x, b);
            a = __dp4a((int)aA[1],  (int)w0.y, a);  b = __dp4a((int)aB[1],  (int)w0.y, b);
            a = __dp4a((int)aA[2],  (int)w0.z, a);  b = __dp4a((int)aB[2],  (int)w0.z, b);
            a = __dp4a((int)aA[3],  (int)w0.w, a);  b = __dp4a((int)aB[3],  (int)w0.w, b);
            a = __dp4a((int)aA[4],  (int)w1.x, a);  b = __dp4a((int)aB[4],  (int)w1.x, b);
            a = __dp4a((int)aA[5],  (int)w1.y, a);  b = __dp4a((int)aB[5],  (int)w1.y, b);
            a = __dp4a((int)aA[6],  (int)w1.z, a);  b = __dp4a((int)aB[6],  (int)w1.z, b);
            a = __dp4a((int)aA[7],  (int)w1.w, a);  b = __dp4a((int)aB[7],  (int)w1.w, b);
            a = __dp4a((int)aA[8],  (int)w2.x, a);  b = __dp4a((int)aB[8],  (int)w2.x, b);
            a = __dp4a((int)aA[9],  (int)w2.y, a);  b = __dp4a((int)aB[9],  (int)w2.y, b);
            a = __dp4a((int)aA[10], (int)w2.z, a);  b = __dp4a((int)aB[10], (int)w2.z, b);
            a = __dp4a((int)aA[11], (int)w2.w, a);  b = __dp4a((int)aB[11], (int)w2.w, b);
            a = __dp4a((int)aA[12], (int)wl,   a);  b = __dp4a((int)aB[12], (int)wl,   b);
            uA[r] = quant_act(a, scale);
            uB[r] = quant_act(b, scale);
        }
        if (jw < 12) {
            oA[jw] = pack4(uA[0], uA[1], uA[2], uA[3]);
            oB[jw] = pack4(uB[0], uB[1], uB[2], uB[3]);
        } else {   // neurons 48,49 + constant-1 byte (bias lane) + zero pad
            oA[12] = (__byte_perm(uA[0], uA[1], 0x0040) & 0xFFFFu) | 0x00010000u;
            oB[12] = (__byte_perm(uB[0], uB[1], 0x0040) & 0xFFFFu) | 0x00010000u;
        }
    }
}

// ---------------------------------------------------------------------------
// K2: build the 255x255 output table; 2 adjacent cells per thread.
// ---------------------------------------------------------------------------
__global__ void __launch_bounds__(128) table_kernel() {
    __shared__ __align__(16) u32 sBuf[PACK_WORDS];
    {
        const uint4* src = reinterpret_cast<const uint4*>(g_packed);
        uint4* dst = reinterpret_cast<uint4*>(sBuf);
        for (int w = threadIdx.x; w < PACK_WORDS / 4; w += 128) dst[w] = src[w];
    }
    __syncthreads();

    int i = blockIdx.x * blockDim.x + threadIdx.x;
    int c0 = i * 2;
    if (c0 >= TBL_SIZE) return;
    bool has1 = (c0 + 1 < TBL_SIZE);
    int c1 = has1 ? c0 + 1 : c0;

    int kz0 = c0 / TBL_DIM - 127, kt0 = c0 % TBL_DIM - 127;
    int kz1 = c1 / TBL_DIM - 127, kt1 = c1 % TBL_DIM - 127;
    u32 aA0 = (u32)(kz0 & 0xFF) | ((u32)(kt0 & 0xFF) << 8) | 0x00010000u;
    u32 aB0 = (u32)(kz1 & 0xFF) | ((u32)(kt1 & 0xFF) << 8) | 0x00010000u;

    u32 xA[13], xB[13], yA[13], yB[13];

    // Layer 1 (fan_in=2; one word per neuron)
    {
        float S1 = __uint_as_float(sBuf[SC_BASE + 1]);
#pragma unroll
        for (int jw = 0; jw < 13; ++jw) {
            const int nj = (jw == 12) ? 2 : 4;
            u32 wv[4];
            if (jw < 12) {
                uint4 w4 = *reinterpret_cast<const uint4*>(&sBuf[W1_BASE + jw * 4]);
                wv[0] = w4.x; wv[1] = w4.y; wv[2] = w4.z; wv[3] = w4.w;
            } else {
                uint2 w2v = *reinterpret_cast<const uint2*>(&sBuf[W1_BASE + 48]);
                wv[0] = w2v.x; wv[1] = w2v.y;
            }
            u32 uA[4], uB[4];
#pragma unroll
            for (int r = 0; r < nj; ++r) {
                uA[r] = quant_act(__dp4a((int)aA0, (int)wv[r], 0), S1);
                uB[r] = quant_act(__dp4a((int)aB0, (int)wv[r], 0), S1);
            }
            if (jw < 12) {
                xA[jw] = pack4(uA[0], uA[1], uA[2], uA[3]);
                xB[jw] = pack4(uB[0], uB[1], uB[2], uB[3]);
            } else {
                xA[12] = (__byte_perm(uA[0], uA[1], 0x0040) & 0xFFFFu) | 0x00010000u;
                xB[12] = (__byte_perm(uB[0], uB[1], 0x0040) & 0xFFFFu) | 0x00010000u;
            }
        }
    }

    hidden_layer2(&sBuf[HID_BASE + 0 * HID_STRIDE], xA, xB, yA, yB, __uint_as_float(sBuf[SC_BASE + 2]));
    hidden_layer2(&sBuf[HID_BASE + 1 * HID_STRIDE], yA, yB, xA, xB, __uint_as_float(sBuf[SC_BASE + 3]));
    hidden_layer2(&sBuf[HID_BASE + 2 * HID_STRIDE], xA, xB, yA, yB, __uint_as_float(sBuf[SC_BASE + 4]));

    // Output layer (2 neurons), both cells
    float So = __uint_as_float(sBuf[SC_BASE + 5]);
    const u32* w0r = &sBuf[WO_BASE];
    const u32* w1r = &sBuf[WO_BASE + ROW_W];
    int a0A = 0, a1A = 0, a0B = 0, a1B = 0;
#pragma unroll
    for (int k = 0; k < 13; ++k) {
        a0A = __dp4a((int)yA[k], (int)w0r[k], a0A);
        a1A = __dp4a((int)yA[k], (int)w1r[k], a1A);
        a0B = __dp4a((int)yB[k], (int)w0r[k], a0B);
        a1B = __dp4a((int)yB[k], (int)w1r[k], a1B);
    }
    float uA0 = (__int_as_float(MAGIC_I + a0A) - MAGIC_F) * So;
    float vA0 = (__int_as_float(MAGIC_I + a1A) - MAGIC_F) * So;
    if (has1) {
        float uB0 = (__int_as_float(MAGIC_I + a0B) - MAGIC_F) * So;
        float vB0 = (__int_as_float(MAGIC_I + a1B) - MAGIC_F) * So;
        *reinterpret_cast<float4*>(&g_table[c0]) = make_float4(uA0, vA0, uB0, vB0);
    } else {
        g_table[c0] = make_float2(uA0, vA0);
    }
}

// ---------------------------------------------------------------------------
// K3: per-sample quantize + table gather; 2 samples per thread
// ---------------------------------------------------------------------------
__device__ __forceinline__ int qcell(float x, float inv) {
    float r = rintf(x * inv);
    r = fminf(fmaxf(r, -127.0f), 127.0f);
    return (int)r + 127;
}

__global__ void __launch_bounds__(256) gather_kernel(const float* __restrict__ z,
                                                     const float* __restrict__ t,
                                                     float* __restrict__ out, int n) {
    int i = blockIdx.x * blockDim.x + threadIdx.x;
    float inv = __uint_as_float(g_packed[SC_BASE + 6]);
    int nv = n >> 1;
    if (i < nv) {
        float2 z2 = reinterpret_cast<const float2*>(z)[i];
        float2 t2 = reinterpret_cast<const float2*>(t)[i];
        int i0 = qcell(z2.x, inv) * TBL_DIM + qcell(t2.x, inv);
        int i1 = qcell(z2.y, inv) * TBL_DIM + qcell(t2.y, inv);
        float2 r0 = g_table[i0];
        float2 r1 = g_table[i1];
        reinterpret_cast<float4*>(out)[i] = make_float4(r0.x, r0.y, r1.x, r1.y);
    }
    if (i == 0) {
        for (int k = nv << 1; k < n; ++k) {       // scalar tail (n odd)
            int idx = qcell(z[k], inv) * TBL_DIM + qcell(t[k], inv);
            float2 r = g_table[idx];
            out[2 * k] = r.x; out[2 * k + 1] = r.y;
        }
    }
}

// ---------------------------------------------------------------------------
extern "C" void kernel_launch(void* const* d_in, const int* in_sizes, int n_in,
                              void* d_out, int out_size) {
    const float* z  = (const float*)d_in[0];
    const float* t  = (const float*)d_in[1];
    const float* W1 = (const float*)d_in[2];
    const float* b1 = (const float*)d_in[3];
    const float* W2 = (const float*)d_in[4];
    const float* b2 = (const float*)d_in[5];
    const float* W3 = (const float*)d_in[6];
    const float* b3 = (const float*)d_in[7];
    const float* W4 = (const float*)d_in[8];
    const float* b4 = (const float*)d_in[9];
    const float* Wo = (const float*)d_in[10];
    const float* bo = (const float*)d_in[11];
    int n = in_sizes[0];

    int total4 = 2 * (n >> 2);                    // combined float4 count
    int nb_in = (total4 + 1023) / 1024;           // 1024 float4 per block (4/thread)
    absmax_prep_kernel<<<nb_in + 5, 256>>>(z, t, n, nb_in,
                                           W1, b1, W2, b2, W3, b3, W4, b4, Wo, bo);
    int tthreads = (TBL_SIZE + 1) / 2;            // 32513
    table_kernel<<<(tthreads + 127) / 128, 128>>>();
    int gthreads = (n + 1) >> 1;
    gather_kernel<<<(gthreads + 255) / 256, 256>>>(z, t, (float*)d_out, n);
}